// round 6
// baseline (speedup 1.0000x reference)
#include <cuda_runtime.h>
#include <cstdint>
#include <math.h>

#define DINL __device__ __forceinline__

// ---------------- problem sizes ----------------
constexpr int B_ = 32, S_ = 1024, D_ = 768, HALF = D_ / 2;
constexpr float QMAXF = 16256.0f;   // 127 * 128

// ---------------- scratch (static device globals) ----------------
__device__ __align__(16) int8_t g_xq1[B_ * S_ * D_], g_xq0[B_ * S_ * D_];
__device__ float g_xs[B_ * S_];
__device__ __align__(16) int8_t g_wq1[3 * D_ * D_], g_wq0[3 * D_ * D_];
__device__ float g_ws[3 * D_];
__device__ __align__(16) float g_Qf[B_ * S_ * D_], g_Kf[B_ * S_ * D_], g_Vtf[B_ * D_ * S_];
__device__ __align__(16) int8_t g_qq1[B_ * S_ * D_], g_qq0[B_ * S_ * D_];
__device__ __align__(16) int8_t g_kq1[B_ * S_ * D_], g_kq0[B_ * S_ * D_];
__device__ float g_qs[B_ * S_], g_ks[B_ * S_];
__device__ __align__(16) int8_t g_vq1[B_ * D_ * S_], g_vq0[B_ * D_ * S_];
__device__ float g_vs[B_ * D_];
__device__ __align__(16) float g_S[(size_t)B_ * S_ * S_];
__device__ __align__(16) int8_t g_pq1[(size_t)B_ * S_ * S_], g_pq0[(size_t)B_ * S_ * S_];
__device__ float g_ps[B_ * S_];
__device__ float g_cosT[S_ * HALF], g_sinT[S_ * HALF];

// ---------------- int8 GEMM tiling ----------------
// CTA tile 128x128, K-chunk 32 (32 bytes/row/digit). smem rows: 8 data words + 4 pad.
constexpr int ROWW  = 12;              // words per smem row
constexpr int TILEW = 128 * ROWW;      // 1536 words per tile
constexpr int BUFW  = 4 * TILEW;       // q1A, q0A, q1B, q0B

// ---------------- helpers ----------------
DINL void imma(int c[4], const uint32_t a[4], const uint32_t b[2]) {
    asm volatile(
        "mma.sync.aligned.m16n8k32.row.col.s32.s8.s8.s32 "
        "{%0,%1,%2,%3}, {%4,%5,%6,%7}, {%8,%9}, {%0,%1,%2,%3};\n"
        : "+r"(c[0]), "+r"(c[1]), "+r"(c[2]), "+r"(c[3])
        : "r"(a[0]), "r"(a[1]), "r"(a[2]), "r"(a[3]), "r"(b[0]), "r"(b[1]));
}

DINL float comb(int x1, int x2) { return 16384.0f * (float)x1 + 128.0f * (float)x2; }

DINL uint32_t pack4(int a, int b, int c, int d) {
    return (a & 0xff) | ((b & 0xff) << 8) | ((c & 0xff) << 16) | ((d & 0xff) << 24);
}

// ---------------- tile LDG / STS ----------------
DINL uint4 ldg_i8(const int8_t* __restrict__ g, int ld, int kt, int tid) {
    int r = tid >> 1, h = tid & 1;
    return *reinterpret_cast<const uint4*>(g + (size_t)r * ld + kt * 32 + h * 16);
}

DINL void sts_i8(uint32_t* smw, uint4 v, int tid) {
    int r = tid >> 1, h = tid & 1;
    *reinterpret_cast<uint4*>(smw + r * ROWW + h * 4) = v;
}

// ---------------- compute one 128x128x32 tile (3-pass int8) ----------------
DINL void compute_i8(const uint32_t* __restrict__ sm, int buf,
                     int c1[4][4][4], int c2[4][4][4]) {
    const int lane = threadIdx.x & 31, warp = threadIdx.x >> 5;
    const int wm = warp >> 2, wn = warp & 3, g = lane >> 2, tg = lane & 3;
    const uint32_t* A1 = sm + buf * BUFW;
    const uint32_t* A0 = A1 + TILEW;
    const uint32_t* B1 = A1 + 2 * TILEW;
    const uint32_t* B0 = A1 + 3 * TILEW;

    uint32_t a1[4][4], a0[4][4];
#pragma unroll
    for (int mf = 0; mf < 4; mf++) {
        int o = (wm * 64 + mf * 16 + g) * ROWW + tg;
        int o8 = o + 8 * ROWW;
        a1[mf][0] = A1[o];     a1[mf][1] = A1[o8];
        a1[mf][2] = A1[o + 4]; a1[mf][3] = A1[o8 + 4];
        a0[mf][0] = A0[o];     a0[mf][1] = A0[o8];
        a0[mf][2] = A0[o + 4]; a0[mf][3] = A0[o8 + 4];
    }
    uint32_t b1[4][2], b0[4][2];
#pragma unroll
    for (int nf = 0; nf < 4; nf++) {
        int o = (wn * 32 + nf * 8 + g) * ROWW + tg;
        b1[nf][0] = B1[o]; b1[nf][1] = B1[o + 4];
        b0[nf][0] = B0[o]; b0[nf][1] = B0[o + 4];
    }
#pragma unroll
    for (int mf = 0; mf < 4; mf++)
#pragma unroll
        for (int nf = 0; nf < 4; nf++) {
            imma(c1[mf][nf], a1[mf], b1[nf]);   // weight 16384
            imma(c2[mf][nf], a1[mf], b0[nf]);   // weight 128
            imma(c2[mf][nf], a0[mf], b1[nf]);   // weight 128
        }
}

// ---------------- int8 GEMM mainloop (double-buffered, R2 structure) ----------------
template <int KT, int LDA, int LDB>
DINL void gemm_i8(const int8_t* __restrict__ A1, const int8_t* __restrict__ A0,
                  const int8_t* __restrict__ B1, const int8_t* __restrict__ B0,
                  uint32_t* smw, int c1[4][4][4], int c2[4][4][4]) {
    const int tid = threadIdx.x;
#pragma unroll
    for (int mf = 0; mf < 4; mf++)
#pragma unroll
        for (int nf = 0; nf < 4; nf++)
#pragma unroll
            for (int r = 0; r < 4; r++) { c1[mf][nf][r] = 0; c2[mf][nf][r] = 0; }

    uint4 va1 = ldg_i8(A1, LDA, 0, tid), va0 = ldg_i8(A0, LDA, 0, tid);
    uint4 vb1 = ldg_i8(B1, LDB, 0, tid), vb0 = ldg_i8(B0, LDB, 0, tid);
    sts_i8(smw, va1, tid);
    sts_i8(smw + TILEW, va0, tid);
    sts_i8(smw + 2 * TILEW, vb1, tid);
    sts_i8(smw + 3 * TILEW, vb0, tid);
    __syncthreads();

    for (int kt = 0; kt < KT; kt++) {
        int buf = kt & 1;
        if (kt + 1 < KT) {
            va1 = ldg_i8(A1, LDA, kt + 1, tid); va0 = ldg_i8(A0, LDA, kt + 1, tid);
            vb1 = ldg_i8(B1, LDB, kt + 1, tid); vb0 = ldg_i8(B0, LDB, kt + 1, tid);
        }
        compute_i8(smw, buf, c1, c2);
        if (kt + 1 < KT) {
            uint32_t* nb = smw + (buf ^ 1) * BUFW;
            sts_i8(nb, va1, tid);
            sts_i8(nb + TILEW, va0, tid);
            sts_i8(nb + 2 * TILEW, vb1, tid);
            sts_i8(nb + 3 * TILEW, vb0, tid);
        }
        __syncthreads();
    }
}

// ---------------- kernel: per-row quantize fp32 -> two s8 digits + scale ----------------
template <int KLEN>
__global__ void __launch_bounds__(256)
k_quant(const float* __restrict__ src, int8_t* __restrict__ d1,
        int8_t* __restrict__ d0, float* __restrict__ sc, int nrows) {
    int w = (blockIdx.x * 256 + threadIdx.x) >> 5;
    if (w >= nrows) return;
    int lane = threadIdx.x & 31;
    const float4* p = reinterpret_cast<const float4*>(src + (size_t)w * KLEN);
    constexpr int NV = KLEN / 128;   // float4s per lane (6 or 8)
    float4 v[NV];
    float mx = 0.0f;
#pragma unroll
    for (int i = 0; i < NV; i++) {
        v[i] = p[lane + 32 * i];
        mx = fmaxf(mx, fmaxf(fmaxf(fabsf(v[i].x), fabsf(v[i].y)),
                             fmaxf(fabsf(v[i].z), fabsf(v[i].w))));
    }
#pragma unroll
    for (int o = 16; o > 0; o >>= 1) mx = fmaxf(mx, __shfl_xor_sync(0xffffffffu, mx, o));
    float s = fmaxf(mx, 1e-30f) * (1.0f / QMAXF);
    float inv = 1.0f / s;
    if (lane == 0) sc[w] = s;
    uint32_t* o1 = reinterpret_cast<uint32_t*>(d1 + (size_t)w * KLEN);
    uint32_t* o0 = reinterpret_cast<uint32_t*>(d0 + (size_t)w * KLEN);
#pragma unroll
    for (int i = 0; i < NV; i++) {
        int q1[4], q0[4];
        const float* pv = reinterpret_cast<const float*>(&v[i]);
#pragma unroll
        for (int j = 0; j < 4; j++) {
            float f = pv[j] * inv;
            q1[j] = __float2int_rn(f * (1.0f / 128.0f));
            q0[j] = __float2int_rn(f - 128.0f * (float)q1[j]);
        }
        o1[lane + 32 * i] = pack4(q1[0], q1[1], q1[2], q1[3]);
        o0[lane + 32 * i] = pack4(q0[0], q0[1], q0[2], q0[3]);
    }
}

// ---------------- kernel: RoPE tables ----------------
__global__ void k_ropetab() {
    int idx = blockIdx.x * 256 + threadIdx.x;
    if (idx >= S_ * HALF) return;
    int s = idx / HALF, i = idx - s * HALF;
    float e = (2.0f * (float)i) / 768.0f;
    float invf = 1.0f / powf(10000.0f, e);
    float ang = (float)s * invf;
    float sn, cs;
    sincosf(ang, &sn, &cs);
    g_cosT[idx] = cs;
    g_sinT[idx] = sn;
}

// ---------------- kernel 1: QKV projection (int8) + bias + RoPE -> fp32 Q/K/Vt ----------------
__global__ void __launch_bounds__(256)
k_qkv(const float* __restrict__ bq, const float* __restrict__ bk, const float* __restrict__ bv) {
    __shared__ uint32_t smw[2 * BUFW];
    int z = blockIdx.z;
    const float* bb = (z == 0) ? bq : (z == 1) ? bk : bv;
    const int bm = blockIdx.y * 128, bn = blockIdx.x * 128;

    int c1[4][4][4], c2[4][4][4];
    gemm_i8<24, D_, D_>(g_xq1 + (size_t)bm * D_, g_xq0 + (size_t)bm * D_,
                        g_wq1 + (size_t)z * D_ * D_ + (size_t)bn * D_,
                        g_wq0 + (size_t)z * D_ * D_ + (size_t)bn * D_,
                        smw, c1, c2);

    const int lane = threadIdx.x & 31, warp = threadIdx.x >> 5;
    const int wm = warp >> 2, wn = warp & 3, g = lane >> 2, tg = lane & 3;
    const float qscale = 0.03608439182435161f;  // 1/sqrt(768)
#pragma unroll
    for (int mf = 0; mf < 4; mf++) {
#pragma unroll
        for (int h = 0; h < 2; h++) {
            int r = bm + wm * 64 + mf * 16 + g + h * 8;
            int s = r & (S_ - 1);
            int b = r >> 10;
            float sa = g_xs[r];
#pragma unroll
            for (int nf = 0; nf < 4; nf++) {
                int col = bn + wn * 32 + nf * 8 + 2 * tg;
                float2 sw = *reinterpret_cast<const float2*>(g_ws + z * D_ + col);
                float2 bia = *reinterpret_cast<const float2*>(bb + col);
                float v0 = comb(c1[mf][nf][h * 2 + 0], c2[mf][nf][h * 2 + 0]) * (sa * sw.x) + bia.x;
                float v1 = comb(c1[mf][nf][h * 2 + 1], c2[mf][nf][h * 2 + 1]) * (sa * sw.y) + bia.y;
                if (z < 2) {
                    int i = col >> 1;
                    float cs = g_cosT[s * HALF + i];
                    float sn = g_sinT[s * HALF + i];
                    float t0 = v0 * cs - v1 * sn;
                    v1 = v0 * sn + v1 * cs;
                    v0 = t0;
                    if (z == 0) { v0 *= qscale; v1 *= qscale; }
                    float* C = (z == 0) ? g_Qf : g_Kf;
                    *reinterpret_cast<float2*>(C + (size_t)r * D_ + col) = make_float2(v0, v1);
                } else {
                    float* Ct = g_Vtf + (size_t)b * D_ * S_;
                    Ct[(size_t)col * S_ + s] = v0;
                    Ct[(size_t)(col + 1) * S_ + s] = v1;
                }
            }
        }
    }
}

// ---------------- kernel 2: scores = (Q*scale) K^T (int8) -> fp32 ----------------
__global__ void __launch_bounds__(256)
k_scores() {
    __shared__ uint32_t smw[2 * BUFW];
    int z = blockIdx.z;
    const int bm = blockIdx.y * 128, bn = blockIdx.x * 128;
    size_t ao = (size_t)z * S_ * D_ + (size_t)bm * D_;
    size_t bo = (size_t)z * S_ * D_ + (size_t)bn * D_;
    float* C = g_S + (size_t)z * S_ * S_;

    int c1[4][4][4], c2[4][4][4];
    gemm_i8<24, D_, D_>(g_qq1 + ao, g_qq0 + ao, g_kq1 + bo, g_kq0 + bo, smw, c1, c2);

    const int lane = threadIdx.x & 31, warp = threadIdx.x >> 5;
    const int wm = warp >> 2, wn = warp & 3, g = lane >> 2, tg = lane & 3;
#pragma unroll
    for (int mf = 0; mf < 4; mf++) {
#pragma unroll
        for (int h = 0; h < 2; h++) {
            int r = bm + wm * 64 + mf * 16 + g + h * 8;
            float sa = g_qs[z * S_ + r];
#pragma unroll
            for (int nf = 0; nf < 4; nf++) {
                int col = bn + wn * 32 + nf * 8 + 2 * tg;
                float2 sk = *reinterpret_cast<const float2*>(g_ks + z * S_ + col);
                float v0 = comb(c1[mf][nf][h * 2 + 0], c2[mf][nf][h * 2 + 0]) * (sa * sk.x);
                float v1 = comb(c1[mf][nf][h * 2 + 1], c2[mf][nf][h * 2 + 1]) * (sa * sk.y);
                *reinterpret_cast<float2*>(C + (size_t)r * S_ + col) = make_float2(v0, v1);
            }
        }
    }
}

// ---------------- kernel 3: row softmax -> int8 digit P + scale ----------------
__global__ void __launch_bounds__(128)
k_softmax() {
    const float* p = g_S + (size_t)blockIdx.x * S_;
    int t = threadIdx.x;
    float4 a = reinterpret_cast<const float4*>(p)[t];
    float4 b = reinterpret_cast<const float4*>(p)[t + 128];

    float m = fmaxf(fmaxf(fmaxf(a.x, a.y), fmaxf(a.z, a.w)),
                    fmaxf(fmaxf(b.x, b.y), fmaxf(b.z, b.w)));
#pragma unroll
    for (int o = 16; o > 0; o >>= 1) m = fmaxf(m, __shfl_xor_sync(0xffffffffu, m, o));
    __shared__ float r1[4], r2[4];
    if ((t & 31) == 0) r1[t >> 5] = m;
    __syncthreads();
    m = fmaxf(fmaxf(r1[0], r1[1]), fmaxf(r1[2], r1[3]));

    a.x = expf(a.x - m); a.y = expf(a.y - m); a.z = expf(a.z - m); a.w = expf(a.w - m);
    b.x = expf(b.x - m); b.y = expf(b.y - m); b.z = expf(b.z - m); b.w = expf(b.w - m);
    float s = a.x + a.y + a.z + a.w + b.x + b.y + b.z + b.w;
#pragma unroll
    for (int o = 16; o > 0; o >>= 1) s += __shfl_xor_sync(0xffffffffu, s, o);
    if ((t & 31) == 0) r2[t >> 5] = s;
    __syncthreads();
    s = r2[0] + r2[1] + r2[2] + r2[3];
    float inv = 1.0f / s;
    if (t == 0) g_ps[blockIdx.x] = inv * (1.0f / QMAXF);

    // quantize un-normalized exp: f = 16256 * e^{x-m}; p ≈ ps * (128 q1 + q0)
    uint32_t* o1 = reinterpret_cast<uint32_t*>(g_pq1 + (size_t)blockIdx.x * S_);
    uint32_t* o0 = reinterpret_cast<uint32_t*>(g_pq0 + (size_t)blockIdx.x * S_);
    const float* ea = reinterpret_cast<const float*>(&a);
    const float* eb = reinterpret_cast<const float*>(&b);
    int q1a[4], q0a[4], q1b[4], q0b[4];
#pragma unroll
    for (int j = 0; j < 4; j++) {
        float fa = ea[j] * QMAXF;
        q1a[j] = __float2int_rn(fa * (1.0f / 128.0f));
        q0a[j] = __float2int_rn(fa - 128.0f * (float)q1a[j]);
        float fb = eb[j] * QMAXF;
        q1b[j] = __float2int_rn(fb * (1.0f / 128.0f));
        q0b[j] = __float2int_rn(fb - 128.0f * (float)q1b[j]);
    }
    o1[t]       = pack4(q1a[0], q1a[1], q1a[2], q1a[3]);
    o0[t]       = pack4(q0a[0], q0a[1], q0a[2], q0a[3]);
    o1[t + 128] = pack4(q1b[0], q1b[1], q1b[2], q1b[3]);
    o0[t + 128] = pack4(q0b[0], q0b[1], q0b[2], q0b[3]);
}

// ---------------- kernel 4: out = P V (int8, NT via transposed V) ----------------
__global__ void __launch_bounds__(256)
k_pv(float* __restrict__ out) {
    __shared__ uint32_t smw[2 * BUFW];
    int z = blockIdx.z;
    const int bm = blockIdx.y * 128, bn = blockIdx.x * 128;
    size_t ao = (size_t)z * S_ * S_ + (size_t)bm * S_;
    size_t bo = (size_t)z * D_ * S_ + (size_t)bn * S_;
    float* C = out + (size_t)z * S_ * D_;

    int c1[4][4][4], c2[4][4][4];
    gemm_i8<32, S_, S_>(g_pq1 + ao, g_pq0 + ao, g_vq1 + bo, g_vq0 + bo, smw, c1, c2);

    const int lane = threadIdx.x & 31, warp = threadIdx.x >> 5;
    const int wm = warp >> 2, wn = warp & 3, g = lane >> 2, tg = lane & 3;
#pragma unroll
    for (int mf = 0; mf < 4; mf++) {
#pragma unroll
        for (int h = 0; h < 2; h++) {
            int r = bm + wm * 64 + mf * 16 + g + h * 8;
            float sa = g_ps[z * S_ + r];
#pragma unroll
            for (int nf = 0; nf < 4; nf++) {
                int col = bn + wn * 32 + nf * 8 + 2 * tg;
                float2 sv = *reinterpret_cast<const float2*>(g_vs + z * D_ + col);
                float v0 = comb(c1[mf][nf][h * 2 + 0], c2[mf][nf][h * 2 + 0]) * (sa * sv.x);
                float v1 = comb(c1[mf][nf][h * 2 + 1], c2[mf][nf][h * 2 + 1]) * (sa * sv.y);
                *reinterpret_cast<float2*>(C + (size_t)r * D_ + col) = make_float2(v0, v1);
            }
        }
    }
}

// ---------------- launch ----------------
extern "C" void kernel_launch(void* const* d_in, const int* in_sizes, int n_in,
                              void* d_out, int out_size) {
    const float* x  = (const float*)d_in[0];
    const float* Wq = (const float*)d_in[1];
    const float* bq = (const float*)d_in[2];
    const float* Wk = (const float*)d_in[3];
    const float* bk = (const float*)d_in[4];
    const float* Wv = (const float*)d_in[5];
    const float* bv = (const float*)d_in[6];
    float* out = (float*)d_out;

    void *xq1, *xq0, *xs, *wq1, *wq0, *ws;
    void *Qf, *Kf, *Vtf, *qq1, *qq0, *kq1, *kq0, *qs, *ks, *vq1, *vq0, *vs;
    cudaGetSymbolAddress(&xq1, g_xq1);  cudaGetSymbolAddress(&xq0, g_xq0);
    cudaGetSymbolAddress(&xs, g_xs);
    cudaGetSymbolAddress(&wq1, g_wq1);  cudaGetSymbolAddress(&wq0, g_wq0);
    cudaGetSymbolAddress(&ws, g_ws);
    cudaGetSymbolAddress(&Qf, g_Qf);    cudaGetSymbolAddress(&Kf, g_Kf);
    cudaGetSymbolAddress(&Vtf, g_Vtf);
    cudaGetSymbolAddress(&qq1, g_qq1);  cudaGetSymbolAddress(&qq0, g_qq0);
    cudaGetSymbolAddress(&kq1, g_kq1);  cudaGetSymbolAddress(&kq0, g_kq0);
    cudaGetSymbolAddress(&qs, g_qs);    cudaGetSymbolAddress(&ks, g_ks);
    cudaGetSymbolAddress(&vq1, g_vq1);  cudaGetSymbolAddress(&vq0, g_vq0);
    cudaGetSymbolAddress(&vs, g_vs);

    k_ropetab<<<(S_ * HALF + 255) / 256, 256>>>();

    // quantize inputs: x rows (32768 x 768), W rows (768 x 768) x3
    k_quant<768><<<(B_ * S_) / 8, 256>>>(x, (int8_t*)xq1, (int8_t*)xq0, (float*)xs, B_ * S_);
    k_quant<768><<<D_ / 8, 256>>>(Wq, (int8_t*)wq1, (int8_t*)wq0, (float*)ws, D_);
    k_quant<768><<<D_ / 8, 256>>>(Wk, (int8_t*)wq1 + (size_t)D_ * D_,
                                  (int8_t*)wq0 + (size_t)D_ * D_, (float*)ws + D_, D_);
    k_quant<768><<<D_ / 8, 256>>>(Wv, (int8_t*)wq1 + 2 * (size_t)D_ * D_,
                                  (int8_t*)wq0 + 2 * (size_t)D_ * D_, (float*)ws + 2 * D_, D_);

    k_qkv<<<dim3(D_ / 128, (B_ * S_) / 128, 3), 256>>>(bq, bk, bv);

    // quantize Q, K (rows of 768) and Vt (rows of 1024)
    k_quant<768><<<(B_ * S_) / 8, 256>>>((float*)Qf, (int8_t*)qq1, (int8_t*)qq0, (float*)qs, B_ * S_);
    k_quant<768><<<(B_ * S_) / 8, 256>>>((float*)Kf, (int8_t*)kq1, (int8_t*)kq0, (float*)ks, B_ * S_);
    k_quant<1024><<<(B_ * D_) / 8, 256>>>((float*)Vtf, (int8_t*)vq1, (int8_t*)vq0, (float*)vs, B_ * D_);

    k_scores<<<dim3(S_ / 128, S_ / 128, B_), 256>>>();
    k_softmax<<<dim3(B_ * S_), 128>>>();
    k_pv<<<dim3(D_ / 128, S_ / 128, B_), 256>>>(out);
}

// round 7
// speedup vs baseline: 2.1654x; 2.1654x over previous
#include <cuda_runtime.h>
#include <cuda_bf16.h>
#include <cstdint>
#include <math.h>

#define DINL __device__ __forceinline__

// ---------------- problem sizes ----------------
constexpr int B_ = 32, S_ = 1024, D_ = 768, HALF = D_ / 2;

// ---------------- scratch (static device globals) ----------------
__device__ __align__(16) __nv_bfloat16 g_xh[B_ * S_ * D_], g_xl[B_ * S_ * D_];
__device__ __align__(16) __nv_bfloat16 g_Wh[3 * D_ * D_], g_Wl[3 * D_ * D_];
__device__ __align__(16) __nv_bfloat16 g_Qh[B_ * S_ * D_], g_Ql[B_ * S_ * D_];
__device__ __align__(16) __nv_bfloat16 g_Kh[B_ * S_ * D_], g_Kl[B_ * S_ * D_];
__device__ __align__(16) __nv_bfloat16 g_Vth[B_ * D_ * S_], g_Vtl[B_ * D_ * S_];
__device__ __align__(16) float g_S[(size_t)B_ * S_ * S_];
__device__ __align__(16) __nv_bfloat16 g_Ph[(size_t)B_ * S_ * S_], g_Pl[(size_t)B_ * S_ * S_];
__device__ float g_cosT[S_ * HALF], g_sinT[S_ * HALF];

// ---------------- tiling ----------------
// CTA tile 128x128, K-chunk 32 bf16. smem rows: 16 data words + 4 pad = 20 words.
constexpr int WStr   = 20;
constexpr int ABUF_W = 128 * WStr;        // 2560 words per tile buffer
constexpr int SMEM_G = 8 * ABUF_W * 4;    // Ah,Al,Bh,Bl x double buffer = 81920 B

constexpr int XN4 = (B_ * S_ * D_) / 4;   // float4 count for x
constexpr int WN4 = (D_ * D_) / 4;        // float4 count per weight

// ---------------- helpers ----------------
DINL uint32_t smem_u32(const void* p) {
    uint32_t a;
    asm("{ .reg .u64 t; cvta.to.shared.u64 t, %1; cvt.u32.u64 %0, t; }" : "=r"(a) : "l"(p));
    return a;
}

DINL uint32_t hi_pack(float a, float b) {  // {bf16_trunc(b), bf16_trunc(a)}, low half = a
    uint32_t r;
    asm("prmt.b32 %0, %1, %2, 0x7632;" : "=r"(r)
        : "r"(__float_as_uint(a)), "r"(__float_as_uint(b)));
    return r;
}

DINL uint32_t lo_pack(float a, float b) {  // rn(residual), low half = a
    float la = a - __uint_as_float(__float_as_uint(a) & 0xffff0000u);
    float lb = b - __uint_as_float(__float_as_uint(b) & 0xffff0000u);
    uint32_t r;
    asm("cvt.rn.bf16x2.f32 %0, %1, %2;" : "=r"(r) : "f"(lb), "f"(la));
    return r;
}

DINL void mma16(float c[4], const uint32_t a[4], const uint32_t b[2]) {
    asm volatile(
        "mma.sync.aligned.m16n8k16.row.col.f32.bf16.bf16.f32 "
        "{%0,%1,%2,%3}, {%4,%5,%6,%7}, {%8,%9}, {%0,%1,%2,%3};\n"
        : "+f"(c[0]), "+f"(c[1]), "+f"(c[2]), "+f"(c[3])
        : "r"(a[0]), "r"(a[1]), "r"(a[2]), "r"(a[3]), "r"(b[0]), "r"(b[1]));
}

// chunk index f (0..511) -> (row, 16B-chunk) with row permutation making
// STS.128 8-lane phases hit rows (j, j+4): banks fully distinct (verified).
DINL void chunk_rc(int f, int& row, int& h) {
    int q = f >> 2;
    h = f & 3;
    row = (q & ~7) | ((q & 1) << 2) | ((q >> 1) & 3);
}

// ---------------- global -> reg (LDG.128), reg -> smem (STS.128) ----------------
template <int LDK>
DINL void ldg_tile(const __nv_bfloat16* __restrict__ g, int kt, uint4 v[2], int tid) {
#pragma unroll
    for (int i = 0; i < 2; i++) {
        int r, h;
        chunk_rc(tid + (i << 8), r, h);
        v[i] = *reinterpret_cast<const uint4*>(g + (size_t)r * LDK + kt * 32 + h * 8);
    }
}

DINL void sts_tile(uint32_t* smw, const uint4 v[2], int tid) {
#pragma unroll
    for (int i = 0; i < 2; i++) {
        int r, h;
        chunk_rc(tid + (i << 8), r, h);
        *reinterpret_cast<uint4*>(smw + r * WStr + h * 4) = v[i];
    }
}

// ---------------- compute one 128x128x32 tile (bf16x3, scalar LDS — R2-proven) ----------------
DINL void compute_tile(const uint32_t* smAh, const uint32_t* smAl,
                       const uint32_t* smBh, const uint32_t* smBl,
                       int buf, float c[4][4][4]) {
    const int lane = threadIdx.x & 31, warp = threadIdx.x >> 5;
    const int wm = warp >> 2, wn = warp & 3, g = lane >> 2, tg = lane & 3;
    const int base = buf * ABUF_W;
#pragma unroll
    for (int kk = 0; kk < 2; kk++) {
        uint32_t ah[4][4], al[4][4];
#pragma unroll
        for (int mf = 0; mf < 4; mf++) {
            int o = base + (wm * 64 + mf * 16 + g) * WStr + kk * 8 + tg;
            int o8 = o + 8 * WStr;
            ah[mf][0] = smAh[o];      al[mf][0] = smAl[o];
            ah[mf][1] = smAh[o8];     al[mf][1] = smAl[o8];
            ah[mf][2] = smAh[o + 4];  al[mf][2] = smAl[o + 4];
            ah[mf][3] = smAh[o8 + 4]; al[mf][3] = smAl[o8 + 4];
        }
        uint32_t bh[4][2], bl[4][2];
#pragma unroll
        for (int nf = 0; nf < 4; nf++) {
            int o = base + (wn * 32 + nf * 8 + g) * WStr + kk * 8 + tg;
            bh[nf][0] = smBh[o]; bh[nf][1] = smBh[o + 4];
            bl[nf][0] = smBl[o]; bl[nf][1] = smBl[o + 4];
        }
#pragma unroll
        for (int mf = 0; mf < 4; mf++)
#pragma unroll
            for (int nf = 0; nf < 4; nf++) {
                mma16(c[mf][nf], ah[mf], bh[nf]);
                mma16(c[mf][nf], ah[mf], bl[nf]);
                mma16(c[mf][nf], al[mf], bh[nf]);
            }
    }
}

// ---------------- GEMM mainloop (double-buffered sync LDG/STS — R2-proven) ----------------
template <int KT, int LDA, int LDB>
DINL void gemm_main(const __nv_bfloat16* __restrict__ Ahg, const __nv_bfloat16* __restrict__ Alg,
                    const __nv_bfloat16* __restrict__ Bhg, const __nv_bfloat16* __restrict__ Blg,
                    uint32_t* sm, float c[4][4][4]) {
    const int tid = threadIdx.x;
    uint32_t* Ah = sm;
    uint32_t* Al = sm + 2 * ABUF_W;
    uint32_t* Bh = sm + 4 * ABUF_W;
    uint32_t* Bl = sm + 6 * ABUF_W;

#pragma unroll
    for (int mf = 0; mf < 4; mf++)
#pragma unroll
        for (int nf = 0; nf < 4; nf++)
#pragma unroll
            for (int r = 0; r < 4; r++) c[mf][nf][r] = 0.0f;

    uint4 vah[2], val_[2], vbh[2], vbl[2];
    ldg_tile<LDA>(Ahg, 0, vah, tid);
    ldg_tile<LDA>(Alg, 0, val_, tid);
    ldg_tile<LDB>(Bhg, 0, vbh, tid);
    ldg_tile<LDB>(Blg, 0, vbl, tid);
    sts_tile(Ah, vah, tid);
    sts_tile(Al, val_, tid);
    sts_tile(Bh, vbh, tid);
    sts_tile(Bl, vbl, tid);
    __syncthreads();

    for (int kt = 0; kt < KT; kt++) {
        int buf = kt & 1;
        if (kt + 1 < KT) {
            ldg_tile<LDA>(Ahg, kt + 1, vah, tid);
            ldg_tile<LDA>(Alg, kt + 1, val_, tid);
            ldg_tile<LDB>(Bhg, kt + 1, vbh, tid);
            ldg_tile<LDB>(Blg, kt + 1, vbl, tid);
        }
        compute_tile(Ah, Al, Bh, Bl, buf, c);
        if (kt + 1 < KT) {
            int nb = (buf ^ 1) * ABUF_W;
            sts_tile(Ah + nb, vah, tid);
            sts_tile(Al + nb, val_, tid);
            sts_tile(Bh + nb, vbh, tid);
            sts_tile(Bl + nb, vbl, tid);
        }
        __syncthreads();
    }
}

// ---------------- kernel 1: all fp32 -> bf16 hi/lo conversions (x + 3 weights) ----------------
__global__ void __launch_bounds__(256)
k_convall(const float* __restrict__ x, const float* __restrict__ Wq,
          const float* __restrict__ Wk, const float* __restrict__ Wv,
          __nv_bfloat16* __restrict__ xh, __nv_bfloat16* __restrict__ xl,
          __nv_bfloat16* __restrict__ wh, __nv_bfloat16* __restrict__ wl) {
    int z = blockIdx.z;
    int i = blockIdx.x * 256 + threadIdx.x;
    const float* src;
    __nv_bfloat16 *dh, *dl;
    int n4;
    if (z == 0) { src = x; dh = xh; dl = xl; n4 = XN4; }
    else {
        src = (z == 1) ? Wq : (z == 2) ? Wk : Wv;
        dh = wh + (size_t)(z - 1) * D_ * D_;
        dl = wl + (size_t)(z - 1) * D_ * D_;
        n4 = WN4;
    }
    if (i >= n4) return;
    float4 v = reinterpret_cast<const float4*>(src)[i];
    uint2 h, l;
    h.x = hi_pack(v.x, v.y); h.y = hi_pack(v.z, v.w);
    l.x = lo_pack(v.x, v.y); l.y = lo_pack(v.z, v.w);
    reinterpret_cast<uint2*>(dh)[i] = h;
    reinterpret_cast<uint2*>(dl)[i] = l;
}

// ---------------- kernel 2: RoPE tables ----------------
__global__ void k_ropetab() {
    int idx = blockIdx.x * 256 + threadIdx.x;
    if (idx >= S_ * HALF) return;
    int s = idx / HALF, i = idx - s * HALF;
    float e = (2.0f * (float)i) / 768.0f;
    float invf = 1.0f / powf(10000.0f, e);
    float ang = (float)s * invf;
    float sn, cs;
    sincosf(ang, &sn, &cs);
    g_cosT[idx] = cs;
    g_sinT[idx] = sn;
}

// ---------------- kernel 3: QKV projection + bias + RoPE -> bf16 hi/lo ----------------
__global__ void __launch_bounds__(256)
k_qkv(const float* __restrict__ bq, const float* __restrict__ bk, const float* __restrict__ bv) {
    extern __shared__ uint32_t sm[];
    int z = blockIdx.z;
    const float* bb = (z == 0) ? bq : (z == 1) ? bk : bv;
    const int bm = blockIdx.y * 128, bn = blockIdx.x * 128;

    float c[4][4][4];
    gemm_main<24, D_, D_>(g_xh + (size_t)bm * D_, g_xl + (size_t)bm * D_,
                          g_Wh + (size_t)z * D_ * D_ + (size_t)bn * D_,
                          g_Wl + (size_t)z * D_ * D_ + (size_t)bn * D_, sm, c);

    const int lane = threadIdx.x & 31, warp = threadIdx.x >> 5;
    const int wm = warp >> 2, wn = warp & 3, g = lane >> 2, tg = lane & 3;
    const float qscale = 0.03608439182435161f;  // 1/sqrt(768)
#pragma unroll
    for (int mf = 0; mf < 4; mf++) {
#pragma unroll
        for (int h = 0; h < 2; h++) {
            int r = bm + wm * 64 + mf * 16 + g + h * 8;
            int s = r & (S_ - 1);
            int b = r >> 10;
#pragma unroll
            for (int nf = 0; nf < 4; nf++) {
                int col = bn + wn * 32 + nf * 8 + 2 * tg;
                float2 bia = *reinterpret_cast<const float2*>(bb + col);
                float v0 = c[mf][nf][h * 2 + 0] + bia.x;
                float v1 = c[mf][nf][h * 2 + 1] + bia.y;
                if (z < 2) {
                    int i = col >> 1;
                    float cs = g_cosT[s * HALF + i];
                    float sn = g_sinT[s * HALF + i];
                    float t0 = v0 * cs - v1 * sn;
                    v1 = v0 * sn + v1 * cs;
                    v0 = t0;
                    if (z == 0) { v0 *= qscale; v1 *= qscale; }
                    __nv_bfloat16* Ch = (z == 0) ? g_Qh : g_Kh;
                    __nv_bfloat16* Cl = (z == 0) ? g_Ql : g_Kl;
                    size_t off = (size_t)r * D_ + col;
                    *reinterpret_cast<uint32_t*>(Ch + off) = hi_pack(v0, v1);
                    *reinterpret_cast<uint32_t*>(Cl + off) = lo_pack(v0, v1);
                } else {
                    size_t boff = (size_t)b * D_ * S_;
                    float h0 = __uint_as_float(__float_as_uint(v0) & 0xffff0000u);
                    float h1 = __uint_as_float(__float_as_uint(v1) & 0xffff0000u);
                    g_Vth[boff + (size_t)col * S_ + s]       = __float2bfloat16(h0);
                    g_Vth[boff + (size_t)(col + 1) * S_ + s] = __float2bfloat16(h1);
                    g_Vtl[boff + (size_t)col * S_ + s]       = __float2bfloat16(v0 - h0);
                    g_Vtl[boff + (size_t)(col + 1) * S_ + s] = __float2bfloat16(v1 - h1);
                }
            }
        }
    }
}

// ---------------- kernel 4: scores = (Q*scale) K^T -> fp32 ----------------
__global__ void __launch_bounds__(256)
k_scores() {
    extern __shared__ uint32_t sm[];
    int z = blockIdx.z;
    const int bm = blockIdx.y * 128, bn = blockIdx.x * 128;
    size_t ao = (size_t)z * S_ * D_ + (size_t)bm * D_;
    size_t bo = (size_t)z * S_ * D_ + (size_t)bn * D_;
    float* C = g_S + (size_t)z * S_ * S_;

    float c[4][4][4];
    gemm_main<24, D_, D_>(g_Qh + ao, g_Ql + ao, g_Kh + bo, g_Kl + bo, sm, c);

    const int lane = threadIdx.x & 31, warp = threadIdx.x >> 5;
    const int wm = warp >> 2, wn = warp & 3, g = lane >> 2, tg = lane & 3;
#pragma unroll
    for (int mf = 0; mf < 4; mf++) {
#pragma unroll
        for (int h = 0; h < 2; h++) {
            int r = bm + wm * 64 + mf * 16 + g + h * 8;
#pragma unroll
            for (int nf = 0; nf < 4; nf++) {
                int col = bn + wn * 32 + nf * 8 + 2 * tg;
                *reinterpret_cast<float2*>(C + (size_t)r * S_ + col) =
                    make_float2(c[mf][nf][h * 2 + 0], c[mf][nf][h * 2 + 1]);
            }
        }
    }
}

// ---------------- kernel 5: row softmax -> bf16 hi/lo P ----------------
__global__ void __launch_bounds__(128)
k_softmax() {
    const float* p = g_S + (size_t)blockIdx.x * S_;
    int t = threadIdx.x;
    float4 a = reinterpret_cast<const float4*>(p)[t];
    float4 b = reinterpret_cast<const float4*>(p)[t + 128];

    float m = fmaxf(fmaxf(fmaxf(a.x, a.y), fmaxf(a.z, a.w)),
                    fmaxf(fmaxf(b.x, b.y), fmaxf(b.z, b.w)));
#pragma unroll
    for (int o = 16; o > 0; o >>= 1) m = fmaxf(m, __shfl_xor_sync(0xffffffffu, m, o));
    __shared__ float r1[4], r2[4];
    if ((t & 31) == 0) r1[t >> 5] = m;
    __syncthreads();
    m = fmaxf(fmaxf(r1[0], r1[1]), fmaxf(r1[2], r1[3]));

    a.x = expf(a.x - m); a.y = expf(a.y - m); a.z = expf(a.z - m); a.w = expf(a.w - m);
    b.x = expf(b.x - m); b.y = expf(b.y - m); b.z = expf(b.z - m); b.w = expf(b.w - m);
    float s = a.x + a.y + a.z + a.w + b.x + b.y + b.z + b.w;
#pragma unroll
    for (int o = 16; o > 0; o >>= 1) s += __shfl_xor_sync(0xffffffffu, s, o);
    if ((t & 31) == 0) r2[t >> 5] = s;
    __syncthreads();
    s = r2[0] + r2[1] + r2[2] + r2[3];
    float inv = 1.0f / s;
    a.x *= inv; a.y *= inv; a.z *= inv; a.w *= inv;
    b.x *= inv; b.y *= inv; b.z *= inv; b.w *= inv;

    uint32_t* ph = reinterpret_cast<uint32_t*>(g_Ph + (size_t)blockIdx.x * S_);
    uint32_t* pl = reinterpret_cast<uint32_t*>(g_Pl + (size_t)blockIdx.x * S_);
    ph[2 * t]       = hi_pack(a.x, a.y);
    ph[2 * t + 1]   = hi_pack(a.z, a.w);
    ph[2 * t + 256] = hi_pack(b.x, b.y);
    ph[2 * t + 257] = hi_pack(b.z, b.w);
    pl[2 * t]       = lo_pack(a.x, a.y);
    pl[2 * t + 1]   = lo_pack(a.z, a.w);
    pl[2 * t + 256] = lo_pack(b.x, b.y);
    pl[2 * t + 257] = lo_pack(b.z, b.w);
}

// ---------------- kernel 6: out = P V (NT via transposed V) ----------------
__global__ void __launch_bounds__(256)
k_pv(float* __restrict__ out) {
    extern __shared__ uint32_t sm[];
    int z = blockIdx.z;
    const int bm = blockIdx.y * 128, bn = blockIdx.x * 128;
    size_t ao = (size_t)z * S_ * S_ + (size_t)bm * S_;
    size_t bo = (size_t)z * D_ * S_ + (size_t)bn * S_;
    float* C = out + (size_t)z * S_ * D_;

    float c[4][4][4];
    gemm_main<32, S_, S_>(g_Ph + ao, g_Pl + ao, g_Vth + bo, g_Vtl + bo, sm, c);

    const int lane = threadIdx.x & 31, warp = threadIdx.x >> 5;
    const int wm = warp >> 2, wn = warp & 3, g = lane >> 2, tg = lane & 3;
#pragma unroll
    for (int mf = 0; mf < 4; mf++) {
#pragma unroll
        for (int h = 0; h < 2; h++) {
            int r = bm + wm * 64 + mf * 16 + g + h * 8;
#pragma unroll
            for (int nf = 0; nf < 4; nf++) {
                int col = bn + wn * 32 + nf * 8 + 2 * tg;
                *reinterpret_cast<float2*>(C + (size_t)r * D_ + col) =
                    make_float2(c[mf][nf][h * 2 + 0], c[mf][nf][h * 2 + 1]);
            }
        }
    }
}

// ---------------- launch ----------------
extern "C" void kernel_launch(void* const* d_in, const int* in_sizes, int n_in,
                              void* d_out, int out_size) {
    const float* x  = (const float*)d_in[0];
    const float* Wq = (const float*)d_in[1];
    const float* bq = (const float*)d_in[2];
    const float* Wk = (const float*)d_in[3];
    const float* bk = (const float*)d_in[4];
    const float* Wv = (const float*)d_in[5];
    const float* bv = (const float*)d_in[6];
    float* out = (float*)d_out;

    cudaFuncSetAttribute(k_qkv,    cudaFuncAttributeMaxDynamicSharedMemorySize, SMEM_G);
    cudaFuncSetAttribute(k_scores, cudaFuncAttributeMaxDynamicSharedMemorySize, SMEM_G);
    cudaFuncSetAttribute(k_pv,     cudaFuncAttributeMaxDynamicSharedMemorySize, SMEM_G);

    void *xh, *xl, *wh, *wl;
    cudaGetSymbolAddress(&xh, g_xh);
    cudaGetSymbolAddress(&xl, g_xl);
    cudaGetSymbolAddress(&wh, g_Wh);
    cudaGetSymbolAddress(&wl, g_Wl);

    // launch order chosen so the 4th launch (ncu capture slot) is k_scores
    k_convall<<<dim3((XN4 + 255) / 256, 1, 4), 256>>>(
        x, Wq, Wk, Wv,
        (__nv_bfloat16*)xh, (__nv_bfloat16*)xl,
        (__nv_bfloat16*)wh, (__nv_bfloat16*)wl);
    k_ropetab<<<(S_ * HALF + 255) / 256, 256>>>();
    k_qkv<<<dim3(D_ / 128, (B_ * S_) / 128, 3), 256, SMEM_G>>>(bq, bk, bv);
    k_scores<<<dim3(S_ / 128, S_ / 128, B_), 256, SMEM_G>>>();
    k_softmax<<<dim3(B_ * S_), 128>>>();
    k_pv<<<dim3(D_ / 128, S_ / 128, B_), 256, SMEM_G>>>(out);
}

// round 8
// speedup vs baseline: 2.2001x; 1.0160x over previous
#include <cuda_runtime.h>
#include <cuda_bf16.h>
#include <cstdint>
#include <math.h>

#define DINL __device__ __forceinline__

// ---------------- problem sizes ----------------
constexpr int B_ = 32, S_ = 1024, D_ = 768, HALF = D_ / 2;

// ---------------- scratch (static device globals) ----------------
__device__ __align__(16) __nv_bfloat16 g_xh[B_ * S_ * D_], g_xl[B_ * S_ * D_];
__device__ __align__(16) __nv_bfloat16 g_Wh[3 * D_ * D_], g_Wl[3 * D_ * D_];
__device__ __align__(16) __nv_bfloat16 g_Qh[B_ * S_ * D_], g_Ql[B_ * S_ * D_];
__device__ __align__(16) __nv_bfloat16 g_Kh[B_ * S_ * D_], g_Kl[B_ * S_ * D_];
__device__ __align__(16) __nv_bfloat16 g_Vth[B_ * D_ * S_], g_Vtl[B_ * D_ * S_];
__device__ __align__(16) float g_S[(size_t)B_ * S_ * S_];
__device__ __align__(16) __nv_bfloat16 g_Ph[(size_t)B_ * S_ * S_], g_Pl[(size_t)B_ * S_ * S_];
__device__ float g_cosT[S_ * HALF], g_sinT[S_ * HALF];

// ---------------- tiling ----------------
// CTA tile 128x128, K-chunk 32 bf16. smem rows: 16 data words + 4 pad = 20 words.
constexpr int WStr   = 20;
constexpr int ABUF_W = 128 * WStr;        // 2560 words per tile buffer
constexpr int SMEM_G = 8 * ABUF_W * 4;    // Ah,Al,Bh,Bl x double buffer = 81920 B

constexpr int XN4 = (B_ * S_ * D_) / 4;
constexpr int WN4 = (D_ * D_) / 4;

// ---------------- helpers ----------------
DINL uint32_t hi_pack(float a, float b) {  // {bf16_trunc(b), bf16_trunc(a)}, low half = a
    uint32_t r;
    asm("prmt.b32 %0, %1, %2, 0x7632;" : "=r"(r)
        : "r"(__float_as_uint(a)), "r"(__float_as_uint(b)));
    return r;
}

DINL uint32_t lo_pack(float a, float b) {  // rn(residual), low half = a
    float la = a - __uint_as_float(__float_as_uint(a) & 0xffff0000u);
    float lb = b - __uint_as_float(__float_as_uint(b) & 0xffff0000u);
    uint32_t r;
    asm("cvt.rn.bf16x2.f32 %0, %1, %2;" : "=r"(r) : "f"(lb), "f"(la));
    return r;
}

DINL void mma16(float c[4], const uint32_t a[4], const uint32_t b[2]) {
    asm volatile(
        "mma.sync.aligned.m16n8k16.row.col.f32.bf16.bf16.f32 "
        "{%0,%1,%2,%3}, {%4,%5,%6,%7}, {%8,%9}, {%0,%1,%2,%3};\n"
        : "+f"(c[0]), "+f"(c[1]), "+f"(c[2]), "+f"(c[3])
        : "r"(a[0]), "r"(a[1]), "r"(a[2]), "r"(a[3]), "r"(b[0]), "r"(b[1]));
}

// chunk index f (0..511) -> (row, 16B-chunk); row permutation keeps STS.128
// 8-lane phases on rows (j, j+4): all 32 banks distinct (verified).
DINL void chunk_rc(int f, int& row, int& h) {
    int q = f >> 2;
    h = f & 3;
    row = (q & ~7) | ((q & 1) << 2) | ((q >> 1) & 3);
}

// load one digit tile (128 rows x 32 bf16) into 2 uint4 staging regs
template <int LDK>
DINL void ldg_tileD(const __nv_bfloat16* __restrict__ g, int kt, uint4 v[2], int tid) {
#pragma unroll
    for (int i = 0; i < 2; i++) {
        int r, h;
        chunk_rc(tid + (i << 8), r, h);
        v[i] = *reinterpret_cast<const uint4*>(g + (size_t)r * LDK + kt * 32 + h * 8);
    }
}

DINL void sts_tileD(uint32_t* smw, const uint4 v[2], int tid) {
#pragma unroll
    for (int i = 0; i < 2; i++) {
        int r, h;
        chunk_rc(tid + (i << 8), r, h);
        *reinterpret_cast<uint4*>(smw + r * WStr + h * 4) = v[i];
    }
}

// ---------------- compute one kk half-chunk (K=16), pass-grouped MMAs ----------------
DINL void compute_kk(const uint32_t* __restrict__ sm, int buf, int kk, float c[4][4][4]) {
    const int lane = threadIdx.x & 31, warp = threadIdx.x >> 5;
    const int wm = warp >> 2, wn = warp & 3, g = lane >> 2, tg = lane & 3;
    const uint32_t* smAh = sm + buf * ABUF_W;
    const uint32_t* smAl = smAh + 2 * ABUF_W;
    const uint32_t* smBh = smAh + 4 * ABUF_W;
    const uint32_t* smBl = smAh + 6 * ABUF_W;

    uint32_t bh[4][2], bl[4][2];
#pragma unroll
    for (int nf = 0; nf < 4; nf++) {
        int o = (wn * 32 + nf * 8 + g) * WStr + kk * 8 + tg;
        bh[nf][0] = smBh[o]; bh[nf][1] = smBh[o + 4];
        bl[nf][0] = smBl[o]; bl[nf][1] = smBl[o + 4];
    }
#pragma unroll
    for (int mf = 0; mf < 4; mf++) {
        int o = (wm * 64 + mf * 16 + g) * WStr + kk * 8 + tg;
        int o8 = o + 8 * WStr;
        uint32_t ah[4] = { smAh[o], smAh[o8], smAh[o + 4], smAh[o8 + 4] };
        uint32_t al[4] = { smAl[o], smAl[o8], smAl[o + 4], smAl[o8 + 4] };
        // pass-grouped: same accumulator reused only every 4 MMAs (no RAW chains)
#pragma unroll
        for (int nf = 0; nf < 4; nf++) mma16(c[mf][nf], ah, bh[nf]);
#pragma unroll
        for (int nf = 0; nf < 4; nf++) mma16(c[mf][nf], ah, bl[nf]);
#pragma unroll
        for (int nf = 0; nf < 4; nf++) mma16(c[mf][nf], al, bh[nf]);
    }
}

// ---------------- GEMM mainloop: double-buffered, A/B staged separately ----------------
template <int KT, int LDA, int LDB>
DINL void gemm_main(const __nv_bfloat16* __restrict__ Ahg, const __nv_bfloat16* __restrict__ Alg,
                    const __nv_bfloat16* __restrict__ Bhg, const __nv_bfloat16* __restrict__ Blg,
                    uint32_t* sm, float c[4][4][4]) {
    const int tid = threadIdx.x;
    uint32_t* Ah = sm;
    uint32_t* Al = sm + 2 * ABUF_W;
    uint32_t* Bh = sm + 4 * ABUF_W;
    uint32_t* Bl = sm + 6 * ABUF_W;

#pragma unroll
    for (int mf = 0; mf < 4; mf++)
#pragma unroll
        for (int nf = 0; nf < 4; nf++)
#pragma unroll
            for (int r = 0; r < 4; r++) c[mf][nf][r] = 0.0f;

    {   // prologue: chunk 0 into buffer 0
        uint4 v0[2], v1[2];
        ldg_tileD<LDA>(Ahg, 0, v0, tid);
        ldg_tileD<LDA>(Alg, 0, v1, tid);
        sts_tileD(Ah, v0, tid);
        sts_tileD(Al, v1, tid);
        ldg_tileD<LDB>(Bhg, 0, v0, tid);
        ldg_tileD<LDB>(Blg, 0, v1, tid);
        sts_tileD(Bh, v0, tid);
        sts_tileD(Bl, v1, tid);
    }
    __syncthreads();

    for (int kt = 0; kt < KT; kt++) {
        int buf = kt & 1;
        int nb = (buf ^ 1) * ABUF_W;
        bool more = (kt + 1 < KT);
        {
            uint4 sah[2], sal[2];
            if (more) {
                ldg_tileD<LDA>(Ahg, kt + 1, sah, tid);
                ldg_tileD<LDA>(Alg, kt + 1, sal, tid);
            }
            compute_kk(sm, buf, 0, c);
            if (more) {
                sts_tileD(Ah + nb, sah, tid);
                sts_tileD(Al + nb, sal, tid);
            }
        }
        {
            uint4 sbh[2], sbl[2];
            if (more) {
                ldg_tileD<LDB>(Bhg, kt + 1, sbh, tid);
                ldg_tileD<LDB>(Blg, kt + 1, sbl, tid);
            }
            compute_kk(sm, buf, 1, c);
            if (more) {
                sts_tileD(Bh + nb, sbh, tid);
                sts_tileD(Bl + nb, sbl, tid);
            }
        }
        __syncthreads();
    }
}

// ---------------- kernel 1: all fp32 -> bf16 hi/lo conversions ----------------
__global__ void __launch_bounds__(256)
k_convall(const float* __restrict__ x, const float* __restrict__ Wq,
          const float* __restrict__ Wk, const float* __restrict__ Wv,
          __nv_bfloat16* __restrict__ xh, __nv_bfloat16* __restrict__ xl,
          __nv_bfloat16* __restrict__ wh, __nv_bfloat16* __restrict__ wl) {
    int z = blockIdx.z;
    int i = blockIdx.x * 256 + threadIdx.x;
    const float* src;
    __nv_bfloat16 *dh, *dl;
    int n4;
    if (z == 0) { src = x; dh = xh; dl = xl; n4 = XN4; }
    else {
        src = (z == 1) ? Wq : (z == 2) ? Wk : Wv;
        dh = wh + (size_t)(z - 1) * D_ * D_;
        dl = wl + (size_t)(z - 1) * D_ * D_;
        n4 = WN4;
    }
    if (i >= n4) return;
    float4 v = reinterpret_cast<const float4*>(src)[i];
    uint2 h, l;
    h.x = hi_pack(v.x, v.y); h.y = hi_pack(v.z, v.w);
    l.x = lo_pack(v.x, v.y); l.y = lo_pack(v.z, v.w);
    reinterpret_cast<uint2*>(dh)[i] = h;
    reinterpret_cast<uint2*>(dl)[i] = l;
}

// ---------------- kernel 2: RoPE tables ----------------
__global__ void k_ropetab() {
    int idx = blockIdx.x * 256 + threadIdx.x;
    if (idx >= S_ * HALF) return;
    int s = idx / HALF, i = idx - s * HALF;
    float e = (2.0f * (float)i) / 768.0f;
    float invf = 1.0f / powf(10000.0f, e);
    float ang = (float)s * invf;
    float sn, cs;
    sincosf(ang, &sn, &cs);
    g_cosT[idx] = cs;
    g_sinT[idx] = sn;
}

// ---------------- kernel 3: QKV projection + bias + RoPE -> bf16 hi/lo ----------------
__global__ void __launch_bounds__(256, 2)
k_qkv(const float* __restrict__ bq, const float* __restrict__ bk, const float* __restrict__ bv) {
    extern __shared__ uint32_t sm[];
    int z = blockIdx.z;
    const float* bb = (z == 0) ? bq : (z == 1) ? bk : bv;
    const int bm = blockIdx.y * 128, bn = blockIdx.x * 128;

    float c[4][4][4];
    gemm_main<24, D_, D_>(g_xh + (size_t)bm * D_, g_xl + (size_t)bm * D_,
                          g_Wh + (size_t)z * D_ * D_ + (size_t)bn * D_,
                          g_Wl + (size_t)z * D_ * D_ + (size_t)bn * D_, sm, c);

    const int lane = threadIdx.x & 31, warp = threadIdx.x >> 5;
    const int wm = warp >> 2, wn = warp & 3, g = lane >> 2, tg = lane & 3;
    const float qscale = 0.03608439182435161f;  // 1/sqrt(768)
#pragma unroll
    for (int mf = 0; mf < 4; mf++) {
#pragma unroll
        for (int h = 0; h < 2; h++) {
            int r = bm + wm * 64 + mf * 16 + g + h * 8;
            int s = r & (S_ - 1);
            int b = r >> 10;
#pragma unroll
            for (int nf = 0; nf < 4; nf++) {
                int col = bn + wn * 32 + nf * 8 + 2 * tg;
                float2 bia = *reinterpret_cast<const float2*>(bb + col);
                float v0 = c[mf][nf][h * 2 + 0] + bia.x;
                float v1 = c[mf][nf][h * 2 + 1] + bia.y;
                if (z < 2) {
                    int i = col >> 1;
                    float cs = g_cosT[s * HALF + i];
                    float sn = g_sinT[s * HALF + i];
                    float t0 = v0 * cs - v1 * sn;
                    v1 = v0 * sn + v1 * cs;
                    v0 = t0;
                    if (z == 0) { v0 *= qscale; v1 *= qscale; }
                    __nv_bfloat16* Ch = (z == 0) ? g_Qh : g_Kh;
                    __nv_bfloat16* Cl = (z == 0) ? g_Ql : g_Kl;
                    size_t off = (size_t)r * D_ + col;
                    *reinterpret_cast<uint32_t*>(Ch + off) = hi_pack(v0, v1);
                    *reinterpret_cast<uint32_t*>(Cl + off) = lo_pack(v0, v1);
                } else {
                    size_t boff = (size_t)b * D_ * S_;
                    float h0 = __uint_as_float(__float_as_uint(v0) & 0xffff0000u);
                    float h1 = __uint_as_float(__float_as_uint(v1) & 0xffff0000u);
                    g_Vth[boff + (size_t)col * S_ + s]       = __float2bfloat16(h0);
                    g_Vth[boff + (size_t)(col + 1) * S_ + s] = __float2bfloat16(h1);
                    g_Vtl[boff + (size_t)col * S_ + s]       = __float2bfloat16(v0 - h0);
                    g_Vtl[boff + (size_t)(col + 1) * S_ + s] = __float2bfloat16(v1 - h1);
                }
            }
        }
    }
}

// ---------------- kernel 4: scores = (Q*scale) K^T -> fp32 ----------------
__global__ void __launch_bounds__(256, 2)
k_scores() {
    extern __shared__ uint32_t sm[];
    int z = blockIdx.z;
    const int bm = blockIdx.y * 128, bn = blockIdx.x * 128;
    size_t ao = (size_t)z * S_ * D_ + (size_t)bm * D_;
    size_t bo = (size_t)z * S_ * D_ + (size_t)bn * D_;
    float* C = g_S + (size_t)z * S_ * S_;

    float c[4][4][4];
    gemm_main<24, D_, D_>(g_Qh + ao, g_Ql + ao, g_Kh + bo, g_Kl + bo, sm, c);

    const int lane = threadIdx.x & 31, warp = threadIdx.x >> 5;
    const int wm = warp >> 2, wn = warp & 3, g = lane >> 2, tg = lane & 3;
#pragma unroll
    for (int mf = 0; mf < 4; mf++) {
#pragma unroll
        for (int h = 0; h < 2; h++) {
            int r = bm + wm * 64 + mf * 16 + g + h * 8;
#pragma unroll
            for (int nf = 0; nf < 4; nf++) {
                int col = bn + wn * 32 + nf * 8 + 2 * tg;
                *reinterpret_cast<float2*>(C + (size_t)r * S_ + col) =
                    make_float2(c[mf][nf][h * 2 + 0], c[mf][nf][h * 2 + 1]);
            }
        }
    }
}

// ---------------- kernel 5: row softmax -> bf16 hi/lo P ----------------
__global__ void __launch_bounds__(128)
k_softmax() {
    const float* p = g_S + (size_t)blockIdx.x * S_;
    int t = threadIdx.x;
    float4 a = reinterpret_cast<const float4*>(p)[t];
    float4 b = reinterpret_cast<const float4*>(p)[t + 128];

    float m = fmaxf(fmaxf(fmaxf(a.x, a.y), fmaxf(a.z, a.w)),
                    fmaxf(fmaxf(b.x, b.y), fmaxf(b.z, b.w)));
#pragma unroll
    for (int o = 16; o > 0; o >>= 1) m = fmaxf(m, __shfl_xor_sync(0xffffffffu, m, o));
    __shared__ float r1[4], r2[4];
    if ((t & 31) == 0) r1[t >> 5] = m;
    __syncthreads();
    m = fmaxf(fmaxf(r1[0], r1[1]), fmaxf(r1[2], r1[3]));

    a.x = expf(a.x - m); a.y = expf(a.y - m); a.z = expf(a.z - m); a.w = expf(a.w - m);
    b.x = expf(b.x - m); b.y = expf(b.y - m); b.z = expf(b.z - m); b.w = expf(b.w - m);
    float s = a.x + a.y + a.z + a.w + b.x + b.y + b.z + b.w;
#pragma unroll
    for (int o = 16; o > 0; o >>= 1) s += __shfl_xor_sync(0xffffffffu, s, o);
    if ((t & 31) == 0) r2[t >> 5] = s;
    __syncthreads();
    s = r2[0] + r2[1] + r2[2] + r2[3];
    float inv = 1.0f / s;
    a.x *= inv; a.y *= inv; a.z *= inv; a.w *= inv;
    b.x *= inv; b.y *= inv; b.z *= inv; b.w *= inv;

    uint32_t* ph = reinterpret_cast<uint32_t*>(g_Ph + (size_t)blockIdx.x * S_);
    uint32_t* pl = reinterpret_cast<uint32_t*>(g_Pl + (size_t)blockIdx.x * S_);
    ph[2 * t]       = hi_pack(a.x, a.y);
    ph[2 * t + 1]   = hi_pack(a.z, a.w);
    ph[2 * t + 256] = hi_pack(b.x, b.y);
    ph[2 * t + 257] = hi_pack(b.z, b.w);
    pl[2 * t]       = lo_pack(a.x, a.y);
    pl[2 * t + 1]   = lo_pack(a.z, a.w);
    pl[2 * t + 256] = lo_pack(b.x, b.y);
    pl[2 * t + 257] = lo_pack(b.z, b.w);
}

// ---------------- kernel 6: out = P V (NT via transposed V) ----------------
__global__ void __launch_bounds__(256, 2)
k_pv(float* __restrict__ out) {
    extern __shared__ uint32_t sm[];
    int z = blockIdx.z;
    const int bm = blockIdx.y * 128, bn = blockIdx.x * 128;
    size_t ao = (size_t)z * S_ * S_ + (size_t)bm * S_;
    size_t bo = (size_t)z * D_ * S_ + (size_t)bn * S_;
    float* C = out + (size_t)z * S_ * D_;

    float c[4][4][4];
    gemm_main<32, S_, S_>(g_Ph + ao, g_Pl + ao, g_Vth + bo, g_Vtl + bo, sm, c);

    const int lane = threadIdx.x & 31, warp = threadIdx.x >> 5;
    const int wm = warp >> 2, wn = warp & 3, g = lane >> 2, tg = lane & 3;
#pragma unroll
    for (int mf = 0; mf < 4; mf++) {
#pragma unroll
        for (int h = 0; h < 2; h++) {
            int r = bm + wm * 64 + mf * 16 + g + h * 8;
#pragma unroll
            for (int nf = 0; nf < 4; nf++) {
                int col = bn + wn * 32 + nf * 8 + 2 * tg;
                *reinterpret_cast<float2*>(C + (size_t)r * D_ + col) =
                    make_float2(c[mf][nf][h * 2 + 0], c[mf][nf][h * 2 + 1]);
            }
        }
    }
}

// ---------------- launch ----------------
extern "C" void kernel_launch(void* const* d_in, const int* in_sizes, int n_in,
                              void* d_out, int out_size) {
    const float* x  = (const float*)d_in[0];
    const float* Wq = (const float*)d_in[1];
    const float* bq = (const float*)d_in[2];
    const float* Wk = (const float*)d_in[3];
    const float* bk = (const float*)d_in[4];
    const float* Wv = (const float*)d_in[5];
    const float* bv = (const float*)d_in[6];
    float* out = (float*)d_out;

    cudaFuncSetAttribute(k_qkv,    cudaFuncAttributeMaxDynamicSharedMemorySize, SMEM_G);
    cudaFuncSetAttribute(k_scores, cudaFuncAttributeMaxDynamicSharedMemorySize, SMEM_G);
    cudaFuncSetAttribute(k_pv,     cudaFuncAttributeMaxDynamicSharedMemorySize, SMEM_G);

    void *xh, *xl, *wh, *wl;
    cudaGetSymbolAddress(&xh, g_xh);
    cudaGetSymbolAddress(&xl, g_xl);
    cudaGetSymbolAddress(&wh, g_Wh);
    cudaGetSymbolAddress(&wl, g_Wl);

    // launch order keeps k_scores in the ncu capture slot (4th launch)
    k_convall<<<dim3((XN4 + 255) / 256, 1, 4), 256>>>(
        x, Wq, Wk, Wv,
        (__nv_bfloat16*)xh, (__nv_bfloat16*)xl,
        (__nv_bfloat16*)wh, (__nv_bfloat16*)wl);
    k_ropetab<<<(S_ * HALF + 255) / 256, 256>>>();
    k_qkv<<<dim3(D_ / 128, (B_ * S_) / 128, 3), 256, SMEM_G>>>(bq, bk, bv);
    k_scores<<<dim3(S_ / 128, S_ / 128, B_), 256, SMEM_G>>>();
    k_softmax<<<dim3(B_ * S_), 128>>>();
    k_pv<<<dim3(D_ / 128, S_ / 128, B_), 256, SMEM_G>>>(out);
}